// round 6
// baseline (speedup 1.0000x reference)
#include <cuda_runtime.h>
#include <cstdint>
#include <math.h>

// ---------------------------------------------------------------------------
// Order1GraphAttentionLayer  (B=4, N=4096, D=256)
//   Ax = feat @ (W@a1)   Ay = feat @ (W@a2)
//   P[i,j] = adj ? ( (Ax[j]+Ay[i])>0 ? e^Ax[j] e^Ay[i] : e^{.2Ax[j]} e^{.2Ay[i]} ) : 0
//   h' = (P @ feat) / rowsum(P)           <- tf32 tensor-core GEMM
//   out = ELU( h' @ W )                   <- fp32 epilogue GEMM
// ---------------------------------------------------------------------------

#define ALPHA  0.2f
#define NB     4
#define NN     4096
#define DDIM   256
#define IT     128                 // i-rows per CTA
#define JT     32                  // j (K) chunk
#define NCHUNK (NN / JT)           // 128
#define MAIN_THREADS 512
#define FSTR   264                 // feat smem row stride (floats), conflict-free B frags
#define PSTR   36                  // P smem row stride (floats), conflict-free A frags

// main-kernel shared memory layout (float offsets)
#define S_AX   0                       // 4096  Ax[j]      (sign test)
#define S_EX   4096                    // 4096  exp(Ax[j])
#define S_EX5  8192                    // 4096  exp(.2Ax[j])
#define S_FB   12288                   // 2 * 32*264 = 16896 feat double buffer
#define S_PB   (12288 + 16896)         // 2 * 128*36 = 9216  P double buffer
#define S_RS   (S_PB + 9216)           // 128   1/rowsum
#define MAIN_SMEM_FLOATS (S_RS + 128)  // 38528
#define MAIN_SMEM_BYTES  (MAIN_SMEM_FLOATS * 4)   // 154112 B

#define EP_THREADS 256
#define EP_ROWS    32
#define EP_SMEM_BYTES ((32 * 256 + 64 * 256) * 4)  // 98304 B

// ---------------- device scratch (allocation-free rule: __device__ globals) --
__device__ float g_featr[(size_t)NB * NN * DDIM];  // feat rounded to tf32 (rna)
__device__ float g_hp   [(size_t)NB * NN * DDIM];  // normalized h'
__device__ float g_wa1[DDIM];
__device__ float g_wa2[DDIM];
__device__ float g_Ax  [NB * NN];
__device__ float g_Ay  [NB * NN];
__device__ float g_exj [NB * NN];   // exp(Ax)
__device__ float g_exj5[NB * NN];   // exp(.2 Ax)
__device__ float g_eyi [NB * NN];   // exp(Ay)
__device__ float g_eyi5[NB * NN];   // exp(.2 Ay)

__device__ __forceinline__ float tf32r(float x) {
    unsigned int u;
    asm("cvt.rna.tf32.f32 %0, %1;" : "=r"(u) : "f"(x));
    return __uint_as_float(u);
}

// ---------------- K1: wa1 = W@a1, wa2 = W@a2 --------------------------------
__global__ void prep_w_kernel(const float* __restrict__ W,
                              const float* __restrict__ a1,
                              const float* __restrict__ a2) {
    int r = blockIdx.x;           // output row 0..255
    int j = threadIdx.x;          // 0..255
    float w  = W[r * DDIM + j];
    float p1 = w * a1[j];
    float p2 = w * a2[j];
    #pragma unroll
    for (int o = 16; o; o >>= 1) {
        p1 += __shfl_xor_sync(0xffffffffu, p1, o);
        p2 += __shfl_xor_sync(0xffffffffu, p2, o);
    }
    __shared__ float s1[8], s2[8];
    int wrp = j >> 5, ln = j & 31;
    if (ln == 0) { s1[wrp] = p1; s2[wrp] = p2; }
    __syncthreads();
    if (j == 0) {
        float t1 = 0.f, t2 = 0.f;
        #pragma unroll
        for (int k = 0; k < 8; k++) { t1 += s1[k]; t2 += s2[k]; }
        g_wa1[r] = t1;
        g_wa2[r] = t2;
    }
}

// ---------------- K2: per-node Ax/Ay dots, exp arrays, feat->tf32 copy ------
__global__ void prep_nodes_kernel(const float* __restrict__ feat) {
    __shared__ float w1s[DDIM], w2s[DDIM];
    int tid = threadIdx.x;
    if (tid < DDIM) { w1s[tid] = g_wa1[tid]; w2s[tid] = g_wa2[tid]; }
    __syncthreads();
    int row = blockIdx.x * 8 + (tid >> 5);   // 2048 blocks * 8 warps -> 16384 rows
    int ln  = tid & 31;
    size_t base = (size_t)row * DDIM + ln * 8;
    float4 v0 = *(const float4*)(feat + base);
    float4 v1 = *(const float4*)(feat + base + 4);
    const float* w1 = w1s + ln * 8;
    const float* w2 = w2s + ln * 8;
    float s1 = v0.x * w1[0] + v0.y * w1[1] + v0.z * w1[2] + v0.w * w1[3]
             + v1.x * w1[4] + v1.y * w1[5] + v1.z * w1[6] + v1.w * w1[7];
    float s2 = v0.x * w2[0] + v0.y * w2[1] + v0.z * w2[2] + v0.w * w2[3]
             + v1.x * w2[4] + v1.y * w2[5] + v1.z * w2[6] + v1.w * w2[7];
    float4 r0, r1;
    r0.x = tf32r(v0.x); r0.y = tf32r(v0.y); r0.z = tf32r(v0.z); r0.w = tf32r(v0.w);
    r1.x = tf32r(v1.x); r1.y = tf32r(v1.y); r1.z = tf32r(v1.z); r1.w = tf32r(v1.w);
    *(float4*)(g_featr + base)     = r0;
    *(float4*)(g_featr + base + 4) = r1;
    #pragma unroll
    for (int o = 16; o; o >>= 1) {
        s1 += __shfl_xor_sync(0xffffffffu, s1, o);
        s2 += __shfl_xor_sync(0xffffffffu, s2, o);
    }
    if (ln == 0) {
        g_Ax  [row] = s1;
        g_exj [row] = expf(s1);
        g_exj5[row] = expf(ALPHA * s1);
        g_Ay  [row] = s2;
        g_eyi [row] = expf(s2);
        g_eyi5[row] = expf(ALPHA * s2);
    }
}

// ---------------- K3: main fused kernel — P gen + tf32 mma P@feat -----------
__global__ __launch_bounds__(MAIN_THREADS, 1)
void gat_main_kernel(const int* __restrict__ adj) {
    extern __shared__ float sm[];
    int tid  = threadIdx.x;
    int b    = blockIdx.x >> 5;            // 32 CTAs per batch
    int i0   = (blockIdx.x & 31) * IT;
    int wrp  = tid >> 5;
    int lane = tid & 31;

    // --- preload j-side arrays for this batch (48 KB) ---
    {
        const float* pax  = g_Ax   + b * NN;
        const float* pex  = g_exj  + b * NN;
        const float* pex5 = g_exj5 + b * NN;
        for (int i = tid; i < NN; i += MAIN_THREADS) {
            sm[S_AX  + i] = pax[i];
            sm[S_EX  + i] = pex[i];
            sm[S_EX5 + i] = pex5[i];
        }
    }
    // --- row-side (fixed per thread for P generation) ---
    int r  = tid >> 2;        // 0..127  (row within i-tile)
    int cg = tid & 3;         // col group: j-cols cg*8 .. cg*8+7
    float rAy  = g_Ay  [b * NN + i0 + r];
    float rey  = g_eyi [b * NN + i0 + r];
    float rey5 = g_eyi5[b * NN + i0 + r];

    const int*   adjbase = adj + (((size_t)(b * NN + i0 + r)) << 12) + cg * 8;
    const float* fgbase  = g_featr + (size_t)b * NN * DDIM;

    float acc[16][4];
    #pragma unroll
    for (int nt = 0; nt < 16; nt++) {
        acc[nt][0] = 0.f; acc[nt][1] = 0.f; acc[nt][2] = 0.f; acc[nt][3] = 0.f;
    }
    float rsum = 0.f;
    float4 fr[4];
    int4   ar[2];

#define LOADG(c) do {                                                          \
        int j0_ = (c) * JT;                                                    \
        const float4* src_ = (const float4*)(fgbase + (size_t)j0_ * DDIM);     \
        fr[0] = src_[tid];                                                     \
        fr[1] = src_[tid +     MAIN_THREADS];                                  \
        fr[2] = src_[tid + 2 * MAIN_THREADS];                                  \
        fr[3] = src_[tid + 3 * MAIN_THREADS];                                  \
        const int4* ap_ = (const int4*)(adjbase + j0_);                        \
        ar[0] = ap_[0];                                                        \
        ar[1] = ap_[1];                                                        \
    } while (0)

#define GENP(c, buf) do {                                                      \
        int j0_ = (c) * JT;                                                    \
        float pq_[8];                                                          \
        _Pragma("unroll")                                                      \
        for (int q = 0; q < 8; q++) {                                          \
            int av_ = (q < 4) ? ((const int*)&ar[0])[q]                        \
                              : ((const int*)&ar[1])[q - 4];                   \
            int j_  = j0_ + cg * 8 + q;                                        \
            float lg_ = sm[S_AX + j_] + rAy;                                   \
            float e_  = (lg_ > 0.f) ? sm[S_EX + j_] * rey                      \
                                    : sm[S_EX5 + j_] * rey5;                   \
            float p_  = (av_ > 0) ? e_ : 0.f;                                  \
            p_ = tf32r(p_);                                                    \
            pq_[q] = p_;                                                       \
            rsum += p_;                                                        \
        }                                                                      \
        float* pb_ = sm + S_PB + (buf) * (IT * PSTR) + r * PSTR + cg * 8;      \
        *(float4*)(pb_)     = make_float4(pq_[0], pq_[1], pq_[2], pq_[3]);     \
        *(float4*)(pb_ + 4) = make_float4(pq_[4], pq_[5], pq_[6], pq_[7]);     \
        float* fb_ = sm + S_FB + (buf) * (JT * FSTR);                          \
        _Pragma("unroll")                                                      \
        for (int k = 0; k < 4; k++) {                                          \
            int f_    = tid + k * MAIN_THREADS;                                \
            int rowj_ = f_ >> 6;                                               \
            int col_  = (f_ & 63) << 2;                                        \
            *(float4*)(fb_ + rowj_ * FSTR + col_) = fr[k];                     \
        }                                                                      \
    } while (0)

#define MMACHUNK(buf) do {                                                     \
        const float* pbF_ = sm + S_PB + (buf) * (IT * PSTR);                   \
        const float* fbF_ = sm + S_FB + (buf) * (JT * FSTR);                   \
        int g_  = lane >> 2;                                                   \
        int tg_ = lane & 3;                                                    \
        int mb_ = (wrp >> 1) * 16;                                             \
        int nb_ = (wrp & 1) * 128;                                             \
        _Pragma("unroll")                                                      \
        for (int ks = 0; ks < 4; ks++) {                                       \
            const unsigned int* pa_ = (const unsigned int*)                    \
                (pbF_ + (mb_ + g_) * PSTR + ks * 8 + tg_);                     \
            unsigned int a0_ = pa_[0];                                         \
            unsigned int a1_ = pa_[8 * PSTR];                                  \
            unsigned int a2_ = pa_[4];                                         \
            unsigned int a3_ = pa_[8 * PSTR + 4];                              \
            const unsigned int* pbb_ = (const unsigned int*)                   \
                (fbF_ + (ks * 8 + tg_) * FSTR + nb_ + g_);                     \
            _Pragma("unroll")                                                  \
            for (int nt = 0; nt < 16; nt++) {                                  \
                unsigned int b0_ = pbb_[nt * 8];                               \
                unsigned int b1_ = pbb_[nt * 8 + 4 * FSTR];                    \
                asm volatile(                                                  \
                  "mma.sync.aligned.m16n8k8.row.col.f32.tf32.tf32.f32 "        \
                  "{%0,%1,%2,%3}, {%4,%5,%6,%7}, {%8,%9}, {%0,%1,%2,%3};\n"   \
                  : "+f"(acc[nt][0]), "+f"(acc[nt][1]),                        \
                    "+f"(acc[nt][2]), "+f"(acc[nt][3])                         \
                  : "r"(a0_), "r"(a1_), "r"(a2_), "r"(a3_),                    \
                    "r"(b0_), "r"(b1_));                                       \
            }                                                                  \
        }                                                                      \
    } while (0)

    // --- software pipeline: LDG(c+1) | mma(c) | P-gen/STS(c+1) | bar ---
    LOADG(0);
    GENP(0, 0);
    __syncthreads();
    for (int c = 0; c < NCHUNK; c++) {
        int cur = c & 1;
        if (c + 1 < NCHUNK) LOADG(c + 1);
        MMACHUNK(cur);
        if (c + 1 < NCHUNK) GENP(c + 1, cur ^ 1);
        __syncthreads();
    }
#undef LOADG
#undef GENP
#undef MMACHUNK

    // --- rowsum reduce (4 threads per row, same warp) ---
    rsum += __shfl_xor_sync(0xffffffffu, rsum, 1);
    rsum += __shfl_xor_sync(0xffffffffu, rsum, 2);
    if (cg == 0) sm[S_RS + r] = 1.0f / rsum;
    __syncthreads();

    // --- scale by 1/rowsum and store h' ---
    {
        int g_  = lane >> 2;
        int tg_ = lane & 3;
        int mb_ = (wrp >> 1) * 16;
        int nb_ = (wrp & 1) * 128;
        float inv0 = sm[S_RS + mb_ + g_];
        float inv1 = sm[S_RS + mb_ + g_ + 8];
        float* hp0 = g_hp + (size_t)(b * NN + i0 + mb_ + g_) * DDIM;
        #pragma unroll
        for (int nt = 0; nt < 16; nt++) {
            int col = nb_ + nt * 8 + tg_ * 2;
            *(float2*)(hp0 + col) =
                make_float2(acc[nt][0] * inv0, acc[nt][1] * inv0);
            *(float2*)(hp0 + 8 * DDIM + col) =
                make_float2(acc[nt][2] * inv1, acc[nt][3] * inv1);
        }
    }
}

// ---------------- K4: epilogue — out = ELU(h' @ W) --------------------------
__global__ __launch_bounds__(EP_THREADS)
void gat_epilogue_kernel(const float* __restrict__ W, float* __restrict__ out) {
    extern __shared__ float es[];
    float* hs = es;            // 32 x 256
    float* Ws = es + 8192;     // 64 x 256 (K chunk)
    int tid  = threadIdx.x;
    int wrp  = tid >> 5;
    int lane = tid & 31;
    int R0   = blockIdx.x * EP_ROWS;

    {   // stage h' rows
        const float4* src = (const float4*)(g_hp + (size_t)R0 * DDIM);
        float4* dst = (float4*)hs;
        #pragma unroll
        for (int k = 0; k < 8; k++)
            dst[tid + k * EP_THREADS] = src[tid + k * EP_THREADS];
    }

    float acc[4][8];
    #pragma unroll
    for (int s = 0; s < 4; s++)
        #pragma unroll
        for (int q = 0; q < 8; q++) acc[s][q] = 0.f;

    for (int kc = 0; kc < 4; kc++) {
        __syncthreads();
        const float4* wsrc = (const float4*)(W + kc * 64 * DDIM);
        float4* wdst = (float4*)Ws;
        #pragma unroll
        for (int k = 0; k < 16; k++)
            wdst[tid + k * EP_THREADS] = wsrc[tid + k * EP_THREADS];
        __syncthreads();
        for (int k = 0; k < 64; k++) {
            float wv[8];
            #pragma unroll
            for (int q = 0; q < 8; q++)
                wv[q] = Ws[k * DDIM + lane + 32 * q];   // conflict-free
            #pragma unroll
            for (int s = 0; s < 4; s++) {
                float h = hs[(wrp + 8 * s) * DDIM + kc * 64 + k];  // broadcast
                #pragma unroll
                for (int q = 0; q < 8; q++) acc[s][q] += h * wv[q];
            }
        }
    }
    #pragma unroll
    for (int s = 0; s < 4; s++) {
        int row = R0 + wrp + 8 * s;
        float* op = out + (size_t)row * DDIM;
        #pragma unroll
        for (int q = 0; q < 8; q++) {
            float v = acc[s][q];
            op[lane + 32 * q] = (v > 0.f) ? v : (expf(v) - 1.0f);
        }
    }
}

// ---------------------------------------------------------------------------
extern "C" void kernel_launch(void* const* d_in, const int* in_sizes, int n_in,
                              void* d_out, int out_size) {
    const float* feat = (const float*)d_in[0];
    const int*   adj  = (const int*)d_in[1];
    const float* W    = (const float*)d_in[2];
    const float* a1   = (const float*)d_in[3];
    const float* a2   = (const float*)d_in[4];
    float* out = (float*)d_out;

    cudaFuncSetAttribute(gat_main_kernel,
                         cudaFuncAttributeMaxDynamicSharedMemorySize,
                         MAIN_SMEM_BYTES);
    cudaFuncSetAttribute(gat_epilogue_kernel,
                         cudaFuncAttributeMaxDynamicSharedMemorySize,
                         EP_SMEM_BYTES);

    prep_w_kernel    <<<256, 256>>>(W, a1, a2);
    prep_nodes_kernel<<<2048, 256>>>(feat);
    gat_main_kernel  <<<NB * (NN / IT), MAIN_THREADS, MAIN_SMEM_BYTES>>>(adj);
    gat_epilogue_kernel<<<(NB * NN) / EP_ROWS, EP_THREADS, EP_SMEM_BYTES>>>(W, out);
    (void)in_sizes; (void)n_in; (void)out_size;
}